// round 8
// baseline (speedup 1.0000x reference)
#include <cuda_runtime.h>
#include <stdint.h>
#include <math.h>

#define BATCH  512
#define TLEN   32768
#define NTH    256
#define CHUNK  4096                  // samples per chunk (16 KB)
#define NCHUNK (TLEN / CHUNK)        // 8
#define NBUF   3                     // triple buffer -> depth-2/3 prefetch
#define BUFSZ  (NTH * 16)            // 4096 floats (swizzled, no pad)
// extras: warpsum 16 + scf 8 + sQ 32 + sh 32 = 88 floats
#define SMEM_FLOATS (NBUF * BUFSZ + 88)
#define SMEM_BYTES  (SMEM_FLOATS * 4)

// ---------------------------------------------------------------------------
__device__ __forceinline__ void dsvf_step(float x, float b0, float b1, float b2,
                                          float na1, float na2,
                                          float& z1, float& z2, float& y) {
    y = fmaf(b0, x, z1);
    z1 = fmaf(na1, y, fmaf(b1, x, z2));
    z2 = fmaf(na2, y, b2 * x);
}

__device__ __forceinline__ void cp_async16(unsigned int dst, const float* src) {
    asm volatile("cp.async.cg.shared.global [%0], [%1], 16;\n" ::
                 "r"(dst), "l"(src));
}

// stage one chunk into swizzled-transposed smem: element e -> row e>>4,
// float4-group (e>>2)&3 XOR'd with (row>>1)&3 (conflict-free .128 access)
__device__ __forceinline__ void load_chunk(const float* __restrict__ g,
                                           unsigned int sbuf, int tid) {
#pragma unroll
    for (int i = 0; i < 4; i++) {
        int f = i * NTH + tid;                    // float4 index in chunk
        int rr = f >> 2, cc = f & 3;
        unsigned int off = (unsigned int)((rr * 16 + ((cc ^ ((rr >> 1) & 3)) << 2)) * 4);
        cp_async16(sbuf + off, g + f * 4);
    }
    asm volatile("cp.async.commit_group;\n");
}

// intra-warp inclusive matrix-monoid scan (Q from smem, broadcast)
__device__ __forceinline__ void warp_scan(float& s1, float& s2,
                                          const float* sQ, int l) {
#pragma unroll
    for (int d = 0; d < 5; d++) {
        int o = 1 << d;
        float q0 = sQ[4 * d + 0], q1 = sQ[4 * d + 1];
        float q2 = sQ[4 * d + 2], q3 = sQ[4 * d + 3];
        float u1 = __shfl_up_sync(0xffffffffu, s1, o);
        float u2 = __shfl_up_sync(0xffffffffu, s2, o);
        if (l >= o) {
            s1 = fmaf(q0, u1, fmaf(q1, u2, s1));
            s2 = fmaf(q2, u1, fmaf(q3, u2, s2));
        }
    }
}

// ---------------------------------------------------------------------------
__global__ void __launch_bounds__(NTH, 4)
dsvf_fused_kernel(const float* __restrict__ x, float* __restrict__ out,
                  const float* __restrict__ g_raw, const float* __restrict__ r_raw,
                  const float* __restrict__ m_hp, const float* __restrict__ m_bp,
                  const float* __restrict__ m_lp) {
    extern __shared__ float sm[];
    float* warpsum = sm + NBUF * BUFSZ;   // 16 floats
    float* scf     = warpsum + 16;        // 8 floats (5 used)
    float* sQ      = scf + 8;             // 32 floats: Q[k] = A^(16*2^k), k=0..7
    float* sh      = sQ + 32;             // 32 floats: h[k] = e1^T A^k, k=0..15

    const int tid = threadIdx.x;
    const int w = tid >> 5, l = tid & 31;
    const int sw = (tid >> 1) & 3;        // this thread's row swizzle

    const float* xrow = x + (size_t)blockIdx.x * TLEN;
    float* yrow = out + (size_t)blockIdx.x * TLEN;

    unsigned int sb[NBUF];
#pragma unroll
    for (int i = 0; i < NBUF; i++)
        sb[i] = (unsigned int)__cvta_generic_to_shared(sm + i * BUFSZ);

    // prefetch chunks 0,1,2 so the scalar coeff math overlaps the loads
    load_chunk(xrow,             sb[0], tid);
    load_chunk(xrow + CHUNK,     sb[1], tid);
    load_chunk(xrow + 2 * CHUNK, sb[2], tid);

    if (tid == 0) {
        float sg = 1.0f / (1.0f + expf(-g_raw[0]));
        float gg = tanf(3.14159265358979323846f * sg * 0.5f);
        float rr = log1pf(expf(r_raw[0]));
        float g2 = gg * gg;
        float hp = m_hp[0], bp = m_bp[0], lp = m_lp[0];

        float b0 = g2 * lp + gg * bp + hp;
        float b1 = 2.0f * g2 * lp - 2.0f * hp;
        float b2 = g2 * lp - gg * bp + hp;
        float a0 = g2 + 2.0f * rr * gg + 1.0f;
        float a1 = 2.0f * g2 - 2.0f;
        float a2 = g2 - 2.0f * rr * gg + 1.0f;
        float inv = 1.0f / a0;
        b0 *= inv; b1 *= inv; b2 *= inv; a1 *= inv; a2 *= inv;
        scf[0] = b0; scf[1] = b1; scf[2] = b2; scf[3] = a1; scf[4] = a2;

        // h[k] = first row of A^k, A = [[-a1,1],[-a2,0]]  (k = 0..15)
        float h1 = 1.f, h2 = 0.f;
#pragma unroll
        for (int k = 0; k < 16; k++) {
            sh[2 * k] = h1; sh[2 * k + 1] = h2;
            float n1 = fmaf(-a1, h1, -a2 * h2);   // h*A: (h1,h2) -> (-a1*h1-a2*h2, h1)
            h2 = h1; h1 = n1;
        }

        // Q[k] = A^(16*2^k), k = 0..7 (double precision squarings)
        double m00 = -(double)a1, m01 = 1.0, m10 = -(double)a2, m11 = 0.0;
#pragma unroll
        for (int i = 0; i < 4; i++) {   // A -> A^16
            double t00 = m00 * m00 + m01 * m10, t01 = m00 * m01 + m01 * m11;
            double t10 = m10 * m00 + m11 * m10, t11 = m10 * m01 + m11 * m11;
            m00 = t00; m01 = t01; m10 = t10; m11 = t11;
        }
        sQ[0] = (float)m00; sQ[1] = (float)m01; sQ[2] = (float)m10; sQ[3] = (float)m11;
#pragma unroll
        for (int k = 1; k < 8; k++) {
            double t00 = m00 * m00 + m01 * m10, t01 = m00 * m01 + m01 * m11;
            double t10 = m10 * m00 + m11 * m10, t11 = m10 * m01 + m11 * m11;
            m00 = t00; m01 = t01; m10 = t10; m11 = t11;
            sQ[4 * k + 0] = (float)m00; sQ[4 * k + 1] = (float)m01;
            sQ[4 * k + 2] = (float)m10; sQ[4 * k + 3] = (float)m11;
        }
    }
    __syncthreads();   // scf/sQ/sh published (prefetches still in flight)

    const float b0 = scf[0], b1 = scf[1], b2 = scf[2];
    const float na1 = -scf[3], na2 = -scf[4];

    // ---- per-lane matrix P = A^(16*l) exclusive (powers of A commute) ----
    float P00 = sQ[0], P01 = sQ[1], P10 = sQ[2], P11 = sQ[3];   // A^16
#pragma unroll
    for (int d = 0; d < 5; d++) {
        int o = 1 << d;
        float u00 = __shfl_up_sync(0xffffffffu, P00, o);
        float u01 = __shfl_up_sync(0xffffffffu, P01, o);
        float u10 = __shfl_up_sync(0xffffffffu, P10, o);
        float u11 = __shfl_up_sync(0xffffffffu, P11, o);
        if (l >= o) {
            float n00 = P00 * u00 + P01 * u10, n01 = P00 * u01 + P01 * u11;
            float n10 = P10 * u00 + P11 * u10, n11 = P10 * u01 + P11 * u11;
            P00 = n00; P01 = n01; P10 = n10; P11 = n11;
        }
    }
    {   // exclusive shift; lane 0 = identity
        float e00 = __shfl_up_sync(0xffffffffu, P00, 1);
        float e01 = __shfl_up_sync(0xffffffffu, P01, 1);
        float e10 = __shfl_up_sync(0xffffffffu, P10, 1);
        float e11 = __shfl_up_sync(0xffffffffu, P11, 1);
        if (l == 0) { e00 = 1.f; e01 = 0.f; e10 = 0.f; e11 = 1.f; }
        P00 = e00; P01 = e01; P10 = e10; P11 = e11;
    }

    float c1 = 0.f, c2 = 0.f;   // chunk carry (identical in every thread)

#pragma unroll
    for (int c = 0; c < NCHUNK; c++) {
        float* b = sm + (c % NBUF) * BUFSZ;
        if (c < NCHUNK - 2)       asm volatile("cp.async.wait_group 2;\n");
        else if (c == NCHUNK - 2) asm volatile("cp.async.wait_group 1;\n");
        else                      asm volatile("cp.async.wait_group 0;\n");
        __syncthreads();   // [BAR1] chunk c resident for all threads

        // ---- pass 1: zero-state recurrence; y0 kept in registers ----
        const float4* rp = reinterpret_cast<const float4*>(b + tid * 16);
        float y0[16];
        float z1 = 0.f, z2 = 0.f;
#pragma unroll
        for (int k = 0; k < 4; k++) {
            float4 xv = rp[k ^ sw];
            dsvf_step(xv.x, b0, b1, b2, na1, na2, z1, z2, y0[4 * k + 0]);
            dsvf_step(xv.y, b0, b1, b2, na1, na2, z1, z2, y0[4 * k + 1]);
            dsvf_step(xv.z, b0, b1, b2, na1, na2, z1, z2, y0[4 * k + 2]);
            dsvf_step(xv.w, b0, b1, b2, na1, na2, z1, z2, y0[4 * k + 3]);
        }

        // ---- intra-warp inclusive scan of per-thread final states ----
        float s1 = z1, s2 = z2;
        warp_scan(s1, s2, sQ, l);
        if (l == 31) { warpsum[2 * w] = s1; warpsum[2 * w + 1] = s2; }
        __syncthreads();   // [BAR2] warpsums visible; ALL pass-1 reads of buf done

        // buffer (c % NBUF) is free now: refill for chunk c+3
        if (c + NBUF < NCHUNK)
            load_chunk(xrow + (c + NBUF) * CHUNK, sb[(c + NBUF) % NBUF], tid);

        // ---- cross-warp scan, redundantly in EVERY warp (lanes 0..7) ----
        float t1 = 0.f, t2 = 0.f;
        if (l < 8) { t1 = warpsum[2 * l]; t2 = warpsum[2 * l + 1]; }
        if (l == 0) {   // fold carry: t0 = Q5*c + t0  (Q5 = A^512)
            t1 = fmaf(sQ[20], c1, fmaf(sQ[21], c2, t1));
            t2 = fmaf(sQ[22], c1, fmaf(sQ[23], c2, t2));
        }
#pragma unroll
        for (int d = 0; d < 3; d++) {   // levels use Q[5+d] = A^(512*2^d)
            int o = 1 << d;
            float q0 = sQ[4 * (5 + d) + 0], q1 = sQ[4 * (5 + d) + 1];
            float q2 = sQ[4 * (5 + d) + 2], q3 = sQ[4 * (5 + d) + 3];
            float u1 = __shfl_up_sync(0xffffffffu, t1, o);
            float u2 = __shfl_up_sync(0xffffffffu, t2, o);
            if (l >= o && l < 8) {
                t1 = fmaf(q0, u1, fmaf(q1, u2, t1));
                t2 = fmaf(q2, u1, fmaf(q3, u2, t2));
            }
        }
        // warp entry E = inclusive total of warp w-1 (carry for w==0)
        float E1 = __shfl_sync(0xffffffffu, t1, (w > 0) ? (w - 1) : 0);
        float E2 = __shfl_sync(0xffffffffu, t2, (w > 0) ? (w - 1) : 0);
        if (w == 0) { E1 = c1; E2 = c2; }
        // next chunk's carry = inclusive total of warp 7
        c1 = __shfl_sync(0xffffffffu, t1, 7);
        c2 = __shfl_sync(0xffffffffu, t2, 7);

        // ---- thread entry state = s_{l-1} + P_l * E ----
        float p1 = __shfl_up_sync(0xffffffffu, s1, 1);
        float p2 = __shfl_up_sync(0xffffffffu, s2, 1);
        if (l == 0) { p1 = 0.f; p2 = 0.f; }
        float e1 = fmaf(P00, E1, fmaf(P01, E2, p1));
        float e2 = fmaf(P10, E1, fmaf(P11, E2, p2));

        // ---- correction + direct store: y_k = y0_k + h[k] . entry ----
        float4* go = reinterpret_cast<float4*>(yrow + c * CHUNK + tid * 16);
#pragma unroll
        for (int k = 0; k < 4; k++) {
            float4 o;
            o.x = fmaf(sh[8 * k + 0], e1, fmaf(sh[8 * k + 1], e2, y0[4 * k + 0]));
            o.y = fmaf(sh[8 * k + 2], e1, fmaf(sh[8 * k + 3], e2, y0[4 * k + 1]));
            o.z = fmaf(sh[8 * k + 4], e1, fmaf(sh[8 * k + 5], e2, y0[4 * k + 2]));
            o.w = fmaf(sh[8 * k + 6], e1, fmaf(sh[8 * k + 7], e2, y0[4 * k + 3]));
            go[k] = o;
        }
        // no trailing barrier: next iteration's BAR1 orders everything needed
    }
}

// ---------------------------------------------------------------------------
extern "C" void kernel_launch(void* const* d_in, const int* in_sizes, int n_in,
                              void* d_out, int out_size) {
    const float* x    = (const float*)d_in[0];
    const float* g    = (const float*)d_in[1];
    const float* r    = (const float*)d_in[2];
    const float* m_hp = (const float*)d_in[3];
    const float* m_bp = (const float*)d_in[4];
    const float* m_lp = (const float*)d_in[5];
    float* out = (float*)d_out;

    cudaFuncSetAttribute(dsvf_fused_kernel,
                         cudaFuncAttributeMaxDynamicSharedMemorySize, SMEM_BYTES);

    dsvf_fused_kernel<<<BATCH, NTH, SMEM_BYTES>>>(x, out, g, r, m_hp, m_bp, m_lp);
}

// round 9
// speedup vs baseline: 1.0663x; 1.0663x over previous
#include <cuda_runtime.h>
#include <stdint.h>
#include <math.h>

#define BATCH  512
#define TLEN   32768
#define NTH    256
#define CHUNK  8192                  // samples per chunk (32 KB)
#define NCHUNK (TLEN / CHUNK)        // 4
#define LSUB   32                    // samples per thread per chunk
#define NBUF   2
#define BUFSZ  (NTH * 32)            // 8192 floats, swizzled 128B rows
// extras: warpsum 16 + scf 8 + sQ 32 + sW 64 = 120 floats
#define SMEM_FLOATS (NBUF * BUFSZ + 120)
#define SMEM_BYTES  (SMEM_FLOATS * 4)

// ---------------------------------------------------------------------------
__device__ __forceinline__ void dsvf_step(float x, float b0, float b1, float b2,
                                          float na1, float na2,
                                          float& z1, float& z2, float& y) {
    y = fmaf(b0, x, z1);
    z1 = fmaf(na1, y, fmaf(b1, x, z2));
    z2 = fmaf(na2, y, b2 * x);
}

__device__ __forceinline__ void cp_async16(unsigned int dst, const float* src) {
    asm volatile("cp.async.cg.shared.global [%0], [%1], 16;\n" ::
                 "r"(dst), "l"(src));
}

// stage one chunk: element e -> row e>>5 (one row per thread, 128B),
// float4-group (e>>2)&7 stored at group ((e>>2)&7) ^ (row&7)  (conflict-free)
__device__ __forceinline__ void load_chunk(const float* __restrict__ g,
                                           unsigned int sbuf, int tid) {
#pragma unroll
    for (int i = 0; i < 8; i++) {
        int f = i * NTH + tid;                    // float4 index in chunk
        int rr = f >> 3, cc = f & 7;
        unsigned int off = (unsigned int)((rr * 32 + ((cc ^ (rr & 7)) << 2)) * 4);
        cp_async16(sbuf + off, g + f * 4);
    }
    asm volatile("cp.async.commit_group;\n");
}

// intra-warp inclusive matrix-monoid scan (Q from smem, broadcast)
__device__ __forceinline__ void warp_scan(float& s1, float& s2,
                                          const float* sQ, int l) {
#pragma unroll
    for (int d = 0; d < 5; d++) {
        int o = 1 << d;
        float q0 = sQ[4 * d + 0], q1 = sQ[4 * d + 1];
        float q2 = sQ[4 * d + 2], q3 = sQ[4 * d + 3];
        float u1 = __shfl_up_sync(0xffffffffu, s1, o);
        float u2 = __shfl_up_sync(0xffffffffu, s2, o);
        if (l >= o) {
            s1 = fmaf(q0, u1, fmaf(q1, u2, s1));
            s2 = fmaf(q2, u1, fmaf(q3, u2, s2));
        }
    }
}

// ---------------------------------------------------------------------------
__global__ void __launch_bounds__(NTH, 3)
dsvf_fused_kernel(const float* __restrict__ x, float* __restrict__ out,
                  const float* __restrict__ g_raw, const float* __restrict__ r_raw,
                  const float* __restrict__ m_hp, const float* __restrict__ m_bp,
                  const float* __restrict__ m_lp) {
    extern __shared__ float sm[];
    float* warpsum = sm + NBUF * BUFSZ;   // 16 floats
    float* scf     = warpsum + 16;        // 8 floats (5 used)
    float* sQ      = scf + 8;             // 32: Q[k] = A^(32*2^k), k=0..7
    float* sW      = sQ + 32;             // 64: W[k] = A^(31-k)*c interleaved {W1,W2}

    const int tid = threadIdx.x;
    const int w = tid >> 5, l = tid & 31;
    const int swz = tid & 7;              // this thread's row swizzle

    const float* xrow = x + (size_t)blockIdx.x * TLEN;
    float* yrow = out + (size_t)blockIdx.x * TLEN;

    unsigned int sb[NBUF];
#pragma unroll
    for (int i = 0; i < NBUF; i++)
        sb[i] = (unsigned int)__cvta_generic_to_shared(sm + i * BUFSZ);

    // prefetch chunks 0,1 so the scalar setup math overlaps the loads
    load_chunk(xrow,         sb[0], tid);
    load_chunk(xrow + CHUNK, sb[1], tid);

    if (tid == 0) {
        float sg = 1.0f / (1.0f + expf(-g_raw[0]));
        float gg = tanf(3.14159265358979323846f * sg * 0.5f);
        float rr = log1pf(expf(r_raw[0]));
        float g2 = gg * gg;
        float hp = m_hp[0], bp = m_bp[0], lp = m_lp[0];

        float b0 = g2 * lp + gg * bp + hp;
        float b1 = 2.0f * g2 * lp - 2.0f * hp;
        float b2 = g2 * lp - gg * bp + hp;
        float a0 = g2 + 2.0f * rr * gg + 1.0f;
        float a1 = 2.0f * g2 - 2.0f;
        float a2 = g2 - 2.0f * rr * gg + 1.0f;
        float inv = 1.0f / a0;
        b0 *= inv; b1 *= inv; b2 *= inv; a1 *= inv; a2 *= inv;
        scf[0] = b0; scf[1] = b1; scf[2] = b2; scf[3] = a1; scf[4] = a2;

        // input vector c for state update s' = A s + c x
        float cc1 = b1 - a1 * b0;
        float cc2 = b2 - a2 * b0;
        // W[k] = A^(31-k) c  (A = [[-a1,1],[-a2,0]]), stored interleaved
        float w1 = cc1, w2 = cc2;
        for (int k = 31; k >= 0; k--) {
            sW[2 * k] = w1; sW[2 * k + 1] = w2;
            float n1 = fmaf(-a1, w1, w2);
            float n2 = -a2 * w1;
            w1 = n1; w2 = n2;
        }

        // Q[k] = A^(32*2^k), k = 0..7 (double-precision squarings)
        double m00 = -(double)a1, m01 = 1.0, m10 = -(double)a2, m11 = 0.0;
        for (int i = 0; i < 5; i++) {   // A -> A^32
            double t00 = m00 * m00 + m01 * m10, t01 = m00 * m01 + m01 * m11;
            double t10 = m10 * m00 + m11 * m10, t11 = m10 * m01 + m11 * m11;
            m00 = t00; m01 = t01; m10 = t10; m11 = t11;
        }
        sQ[0] = (float)m00; sQ[1] = (float)m01; sQ[2] = (float)m10; sQ[3] = (float)m11;
        for (int k = 1; k < 8; k++) {
            double t00 = m00 * m00 + m01 * m10, t01 = m00 * m01 + m01 * m11;
            double t10 = m10 * m00 + m11 * m10, t11 = m10 * m01 + m11 * m11;
            m00 = t00; m01 = t01; m10 = t10; m11 = t11;
            sQ[4 * k + 0] = (float)m00; sQ[4 * k + 1] = (float)m01;
            sQ[4 * k + 2] = (float)m10; sQ[4 * k + 3] = (float)m11;
        }
    }
    __syncthreads();   // scf/sQ/sW published (prefetches still in flight)

    const float b0 = scf[0], b1 = scf[1], b2 = scf[2];
    const float na1 = -scf[3], na2 = -scf[4];

    // ---- per-lane matrix P = A^(32*l), exclusive (powers of A commute) ----
    float P00 = sQ[0], P01 = sQ[1], P10 = sQ[2], P11 = sQ[3];   // A^32
#pragma unroll
    for (int d = 0; d < 5; d++) {
        int o = 1 << d;
        float u00 = __shfl_up_sync(0xffffffffu, P00, o);
        float u01 = __shfl_up_sync(0xffffffffu, P01, o);
        float u10 = __shfl_up_sync(0xffffffffu, P10, o);
        float u11 = __shfl_up_sync(0xffffffffu, P11, o);
        if (l >= o) {
            float n00 = P00 * u00 + P01 * u10, n01 = P00 * u01 + P01 * u11;
            float n10 = P10 * u00 + P11 * u10, n11 = P10 * u01 + P11 * u11;
            P00 = n00; P01 = n01; P10 = n10; P11 = n11;
        }
    }
    {   // exclusive shift; lane 0 = identity
        float e00 = __shfl_up_sync(0xffffffffu, P00, 1);
        float e01 = __shfl_up_sync(0xffffffffu, P01, 1);
        float e10 = __shfl_up_sync(0xffffffffu, P10, 1);
        float e11 = __shfl_up_sync(0xffffffffu, P11, 1);
        if (l == 0) { e00 = 1.f; e01 = 0.f; e10 = 0.f; e11 = 1.f; }
        P00 = e00; P01 = e01; P10 = e10; P11 = e11;
    }

    float c1 = 0.f, c2 = 0.f;   // chunk carry (identical in every thread)

#pragma unroll
    for (int c = 0; c < NCHUNK; c++) {
        float* b = sm + (c & 1) * BUFSZ;
        if (c < NCHUNK - 1) asm volatile("cp.async.wait_group 1;\n");
        else                asm volatile("cp.async.wait_group 0;\n");
        __syncthreads();   // [BAR1] chunk c resident

        // ---- load this thread's 32 samples into registers (swizzled LDS.128)
        const float4* rp = reinterpret_cast<const float4*>(b + tid * 32);
        float4 xr[8];
#pragma unroll
        for (int k = 0; k < 8; k++) xr[k] = rp[k ^ swz];

        // ---- pass 1: chain-free dot products  v = sum W[k]*x[k] ----
        const float4* W4 = reinterpret_cast<const float4*>(sW);
        float v1a = 0.f, v2a = 0.f, v1b = 0.f, v2b = 0.f;
#pragma unroll
        for (int k = 0; k < 8; k++) {
            float4 wa = W4[2 * k];       // {W1[4k],W2[4k],W1[4k+1],W2[4k+1]}
            float4 wb = W4[2 * k + 1];   // {W1[4k+2],W2[4k+2],W1[4k+3],W2[4k+3]}
            v1a = fmaf(wa.x, xr[k].x, v1a); v2a = fmaf(wa.y, xr[k].x, v2a);
            v1b = fmaf(wa.z, xr[k].y, v1b); v2b = fmaf(wa.w, xr[k].y, v2b);
            v1a = fmaf(wb.x, xr[k].z, v1a); v2a = fmaf(wb.y, xr[k].z, v2a);
            v1b = fmaf(wb.z, xr[k].w, v1b); v2b = fmaf(wb.w, xr[k].w, v2b);
        }
        float z1 = v1a + v1b, z2 = v2a + v2b;

        // ---- intra-warp inclusive scan of per-thread final states ----
        float s1 = z1, s2 = z2;
        warp_scan(s1, s2, sQ, l);
        if (l == 31) { warpsum[2 * w] = s1; warpsum[2 * w + 1] = s2; }
        __syncthreads();   // [BAR2] warpsums visible

        // ---- cross-warp scan, redundantly in EVERY warp (lanes 0..7) ----
        float t1 = 0.f, t2 = 0.f;
        if (l < 8) { t1 = warpsum[2 * l]; t2 = warpsum[2 * l + 1]; }
        if (l == 0) {   // fold carry: t0 = Q5*c + t0  (Q5 = A^1024 = warp block)
            t1 = fmaf(sQ[20], c1, fmaf(sQ[21], c2, t1));
            t2 = fmaf(sQ[22], c1, fmaf(sQ[23], c2, t2));
        }
#pragma unroll
        for (int d = 0; d < 3; d++) {   // levels use Q[5+d] = A^(1024*2^d)
            int o = 1 << d;
            float q0 = sQ[4 * (5 + d) + 0], q1 = sQ[4 * (5 + d) + 1];
            float q2 = sQ[4 * (5 + d) + 2], q3 = sQ[4 * (5 + d) + 3];
            float u1 = __shfl_up_sync(0xffffffffu, t1, o);
            float u2 = __shfl_up_sync(0xffffffffu, t2, o);
            if (l >= o && l < 8) {
                t1 = fmaf(q0, u1, fmaf(q1, u2, t1));
                t2 = fmaf(q2, u1, fmaf(q3, u2, t2));
            }
        }
        // warp entry E = inclusive total of warp w-1 (carry for w==0)
        float E1 = __shfl_sync(0xffffffffu, t1, (w > 0) ? (w - 1) : 0);
        float E2 = __shfl_sync(0xffffffffu, t2, (w > 0) ? (w - 1) : 0);
        if (w == 0) { E1 = c1; E2 = c2; }
        // next chunk's carry = inclusive total of warp 7
        c1 = __shfl_sync(0xffffffffu, t1, 7);
        c2 = __shfl_sync(0xffffffffu, t2, 7);

        // ---- thread entry state = s_{l-1} + P_l * E ----
        float p1 = __shfl_up_sync(0xffffffffu, s1, 1);
        float p2 = __shfl_up_sync(0xffffffffu, s2, 1);
        if (l == 0) { p1 = 0.f; p2 = 0.f; }
        z1 = fmaf(P00, E1, fmaf(P01, E2, p1));
        z2 = fmaf(P10, E1, fmaf(P11, E2, p2));

        // ---- pass 2: filter from registers, write y into smem row ----
        float4* wp = reinterpret_cast<float4*>(b + tid * 32);
#pragma unroll
        for (int k = 0; k < 8; k++) {
            float4 o;
            dsvf_step(xr[k].x, b0, b1, b2, na1, na2, z1, z2, o.x);
            dsvf_step(xr[k].y, b0, b1, b2, na1, na2, z1, z2, o.y);
            dsvf_step(xr[k].z, b0, b1, b2, na1, na2, z1, z2, o.z);
            dsvf_step(xr[k].w, b0, b1, b2, na1, na2, z1, z2, o.w);
            wp[k ^ swz] = o;
        }
        __syncthreads();   // [BAR3] all rows written

        // ---- coalesced store (swizzled LDS.128 -> STG.128) ----
        float4* go4 = reinterpret_cast<float4*>(yrow + c * CHUNK);
#pragma unroll
        for (int i = 0; i < 8; i++) {
            int f = i * NTH + tid;
            int rr = f >> 3, cc = f & 7;
            go4[f] = reinterpret_cast<const float4*>(b + rr * 32)[cc ^ (rr & 7)];
        }
        __syncthreads();   // [BAR4] buffer drained before refill

        if (c + 2 < NCHUNK)
            load_chunk(xrow + (c + 2) * CHUNK, sb[c & 1], tid);
    }
}

// ---------------------------------------------------------------------------
extern "C" void kernel_launch(void* const* d_in, const int* in_sizes, int n_in,
                              void* d_out, int out_size) {
    const float* x    = (const float*)d_in[0];
    const float* g    = (const float*)d_in[1];
    const float* r    = (const float*)d_in[2];
    const float* m_hp = (const float*)d_in[3];
    const float* m_bp = (const float*)d_in[4];
    const float* m_lp = (const float*)d_in[5];
    float* out = (float*)d_out;

    cudaFuncSetAttribute(dsvf_fused_kernel,
                         cudaFuncAttributeMaxDynamicSharedMemorySize, SMEM_BYTES);

    dsvf_fused_kernel<<<BATCH, NTH, SMEM_BYTES>>>(x, out, g, r, m_hp, m_bp, m_lp);
}